// round 15
// baseline (speedup 1.0000x reference)
#include <cuda_runtime.h>
#include <cuda_bf16.h>
#include <cuda_fp16.h>
#include <stdint.h>
#include <math.h>

// Problem constants
#define NN   100000
#define FEAT 64
#define HID  128
#define EE   3200000
#define NP   3
#define ALPHA 0.1f

// ---------------- device scratch (static allocation; no cudaMalloc) ----------------
__device__ __align__(16) float   g_x[NN * FEAT];    // relu(h), also feat0 (fp32)
__device__ __align__(16) float   g_z0[NN * FEAT];   // per-path final features (fp32)
__device__ __align__(16) float   g_z1[NN * FEAT];
__device__ __align__(16) float   g_z2[NN * FEAT];
__device__ __align__(16) __half2 g_hA[NP * NN * 32];  // per-path ping-pong buffers (fp16)
__device__ __align__(16) __half2 g_hB[NP * NN * 32];  //   (pre-scaled by norm_out)
__device__ int   g_csr[NP * EE];      // CSR: src indices grouped by dst
__device__ int   g_rowstart[NP * NN]; // CSR row offsets (per path)
__device__ int   g_fill[NP * NN];     // per-row fill counters
__device__ int   g_ecnt[NP];          // per-path edge counters for block-base grab
__device__ int   g_deg_out[NP * NN];
__device__ int   g_deg_in[NP * NN];
__device__ float g_norm_out[NP * NN];
__device__ float g_norm_in[NP * NN];
__device__ float g_wsum[NP];
__device__ float g_beta[NP];
__device__ int   g_is64;

__device__ __forceinline__ float* zbuf(int p) {
    return p == 0 ? g_z0 : (p == 1 ? g_z1 : g_z2);
}

// two tanh in one MUFU op
__device__ __forceinline__ __half2 tanh_h2(__half2 x) {
    unsigned int xu = *(unsigned int*)&x;
    unsigned int yu;
    asm("tanh.approx.f16x2 %0, %1;" : "=r"(yu) : "r"(xu));
    return *(__half2*)&yu;
}

// read edge index i from src/dst handling either dtype, clamped to [0, NN)
__device__ __forceinline__ int read_idx(const void* buf, int i) {
    long long v = g_is64 ? ((const long long*)buf)[i] : (long long)((const int*)buf)[i];
    int r = (int)v;
    if (r < 0) r = 0;
    if (r >= NN) r = NN - 1;
    return r;
}

// ---------------- kernels ----------------

// Detect whether index buffers are int64 or int32.
__global__ void k_detect(const void* __restrict__ src) {
    const long long* s64 = (const long long*)src;
    int ok = 1;
    for (int i = 0; i < 64; i++) {
        long long v = s64[i];
        if (v < 0 || v >= NN) { ok = 0; break; }
    }
    g_is64 = ok;
}

// x = relu(h); zero degrees, counters, wsum
__global__ void k_init(const float* __restrict__ h) {
    int i = blockIdx.x * blockDim.x + threadIdx.x;
    if (i < NN * FEAT) {
        g_x[i] = fmaxf(h[i], 0.0f);
    }
    if (i < NP * NN) {
        g_deg_out[i] = 0;
        g_deg_in[i]  = 0;
    }
    if (i < NP) { g_wsum[i] = 0.0f; g_ecnt[i] = 0; }
}

// degree histograms straight from the input buffers
__global__ void k_deg(const void* __restrict__ src,
                      const void* __restrict__ dst) {
    int i = blockIdx.x * blockDim.x + threadIdx.x;
    if (i >= NP * EE) return;
    int p = i / EE;
    int s = read_idx(src, i);
    int d = read_idx(dst, i);
    atomicAdd(&g_deg_out[p * NN + s], 1);
    atomicAdd(&g_deg_in[p * NN + d], 1);
}

// norm = clip(deg,1)^-0.5
__global__ void k_norm() {
    int i = blockIdx.x * blockDim.x + threadIdx.x;
    if (i >= NP * NN) return;
    int dOut = g_deg_out[i]; if (dOut < 1) dOut = 1;
    int dIn  = g_deg_in[i];  if (dIn  < 1) dIn  = 1;
    g_norm_out[i] = rsqrtf((float)dOut);
    g_norm_in[i]  = rsqrtf((float)dIn);
}

// CSR row offsets via in-block scan + one atomic per block (grid.y = path)
__global__ void k_rowstart() {
    __shared__ int s[256];
    __shared__ int base;
    int p   = blockIdx.y;
    int tid = threadIdx.x;
    int n   = blockIdx.x * 256 + tid;
    int d   = (n < NN) ? g_deg_in[p * NN + n] : 0;
    s[tid] = d;
    __syncthreads();
    #pragma unroll
    for (int off = 1; off < 256; off <<= 1) {
        int v = (tid >= off) ? s[tid - off] : 0;
        __syncthreads();
        s[tid] += v;
        __syncthreads();
    }
    if (tid == 255) base = atomicAdd(&g_ecnt[p], s[255]);
    __syncthreads();
    if (n < NN) {
        g_rowstart[p * NN + n] = base + s[tid] - d;  // exclusive offset
        g_fill[p * NN + n] = 0;
    }
}

// CSR fill: scatter src index into its dst row (reads inputs directly)
__global__ void k_csrfill(const void* __restrict__ src,
                          const void* __restrict__ dst) {
    int i = blockIdx.x * blockDim.x + threadIdx.x;
    if (i >= NP * EE) return;
    int p = i / EE;
    int s = read_idx(src, i);
    int d = read_idx(dst, i);
    int idx = p * NN + d;
    int slot = atomicAdd(&g_fill[idx], 1);
    g_csr[p * EE + g_rowstart[idx] + slot] = s;
}

// hA[(p,n)] = half2(x[n] * norm_out[p,n])  for ALL paths in one launch
__global__ void k_scale() {
    int i = blockIdx.x * blockDim.x + threadIdx.x;   // half2 slots: NP*NN*32
    if (i >= NP * NN * 32) return;
    int pn = i >> 5;                 // p*NN + n
    int n  = pn % NN;
    float no = g_norm_out[pn];
    float2 x = ((const float2*)g_x)[n * 32 + (i & 31)];
    g_hA[i] = __floats2half2_rn(x.x * no, x.y * no);
}

// gather step for ALL paths: one warp per (path, node).
// mode 0: A->B, 1: B->A, 2: A->z[p] (last).
__global__ void __launch_bounds__(256) k_gather(int mode) {
    int gwarp = (blockIdx.x * blockDim.x + threadIdx.x) >> 5;
    if (gwarp >= NP * NN) return;
    int lane = threadIdx.x & 31;
    int p = gwarp / NN;
    int n = gwarp - p * NN;
    int idx = gwarp;                  // p*NN + n
    int start = g_rowstart[idx];
    int deg   = g_deg_in[idx];
    const int* __restrict__ csr = &g_csr[p * EE + start];
    const __half2* __restrict__ fin =
        ((mode == 1) ? g_hB : g_hA) + (size_t)p * NN * 32;

    float ax = 0.0f, ay = 0.0f;
    int e = 0;
    for (; e + 4 <= deg; e += 4) {
        int s0 = csr[e], s1 = csr[e + 1], s2 = csr[e + 2], s3 = csr[e + 3];
        float2 v0 = __half22float2(fin[s0 * 32 + lane]);
        float2 v1 = __half22float2(fin[s1 * 32 + lane]);
        float2 v2 = __half22float2(fin[s2 * 32 + lane]);
        float2 v3 = __half22float2(fin[s3 * 32 + lane]);
        ax += (v0.x + v1.x) + (v2.x + v3.x);
        ay += (v0.y + v1.y) + (v2.y + v3.y);
    }
    for (; e < deg; e++) {
        float2 v = __half22float2(fin[csr[e] * 32 + lane]);
        ax += v.x;
        ay += v.y;
    }

    float ni = g_norm_in[idx];
    float2 x = ((const float2*)g_x)[n * 32 + lane];
    float vx = 0.9f * ax * ni + ALPHA * x.x;
    float vy = 0.9f * ay * ni + ALPHA * x.y;
    if (mode == 2) {
        ((float2*)zbuf(p))[n * 32 + lane] = make_float2(vx, vy);
    } else {
        float no = g_norm_out[idx];
        __half2* fout = ((mode == 0) ? g_hB : g_hA) + (size_t)p * NN * 32;
        fout[n * 32 + lane] = __floats2half2_rn(vx * no, vy * no);
    }
}

// semantic fusion scores: wsum[p] += sum_n tanh(z[n,p,:]@W1 + b1) @ W2
// tanh evaluated two-at-a-time on the MUFU pipe via tanh.approx.f16x2
__global__ void __launch_bounds__(256) k_fusion(const float* __restrict__ W1,
                                                const float* __restrict__ b1,
                                                const float* __restrict__ W2) {
    __shared__ float sW1[FEAT * HID];   // 32 KB, row k holds W1[k][0..127]
    __shared__ float sb1[HID];
    __shared__ float sW2[HID];
    __shared__ float sred[256];
    int tid = threadIdx.x;
    for (int i = tid; i < FEAT * HID; i += 256) sW1[i] = W1[i];
    if (tid < HID) { sb1[tid] = b1[tid]; sW2[tid] = W2[tid]; }
    __syncthreads();

    int p = blockIdx.y;
    int n = blockIdx.x * 256 + tid;
    float acc = 0.0f;
    if (n < NN) {
        float zr[FEAT];
        const float4* zp = (const float4*)zbuf(p);
        #pragma unroll
        for (int i = 0; i < 16; i++) {
            float4 v = zp[n * 16 + i];
            zr[4 * i + 0] = v.x; zr[4 * i + 1] = v.y;
            zr[4 * i + 2] = v.z; zr[4 * i + 3] = v.w;
        }
        for (int j = 0; j < HID; j += 4) {
            float h0 = sb1[j], h1 = sb1[j + 1], h2 = sb1[j + 2], h3 = sb1[j + 3];
            #pragma unroll
            for (int k = 0; k < FEAT; k++) {
                float4 w = *(const float4*)&sW1[k * HID + j];
                h0 = fmaf(zr[k], w.x, h0);
                h1 = fmaf(zr[k], w.y, h1);
                h2 = fmaf(zr[k], w.z, h2);
                h3 = fmaf(zr[k], w.w, h3);
            }
            float2 t01 = __half22float2(tanh_h2(__floats2half2_rn(h0, h1)));
            float2 t23 = __half22float2(tanh_h2(__floats2half2_rn(h2, h3)));
            acc += t01.x * sW2[j]     + t01.y * sW2[j + 1]
                 + t23.x * sW2[j + 2] + t23.y * sW2[j + 3];
        }
    }
    sred[tid] = acc;
    __syncthreads();
    for (int s = 128; s > 0; s >>= 1) {
        if (tid < s) sred[tid] += sred[tid + s];
        __syncthreads();
    }
    if (tid == 0) atomicAdd(&g_wsum[p], sred[0]);
}

// beta = softmax(wsum / N)
__global__ void k_softmax() {
    float w0 = g_wsum[0] / (float)NN;
    float w1 = g_wsum[1] / (float)NN;
    float w2 = g_wsum[2] / (float)NN;
    float m = fmaxf(w0, fmaxf(w1, w2));
    float e0 = expf(w0 - m), e1 = expf(w1 - m), e2 = expf(w2 - m);
    float s = e0 + e1 + e2;
    g_beta[0] = e0 / s; g_beta[1] = e1 / s; g_beta[2] = e2 / s;
}

// out = sum_p beta[p] * z[p]
__global__ void k_final(float* __restrict__ out) {
    int i = blockIdx.x * blockDim.x + threadIdx.x;   // float4 granularity
    if (i >= NN * 16) return;
    float b0 = g_beta[0], b1 = g_beta[1], b2 = g_beta[2];
    float4 a = ((const float4*)g_z0)[i];
    float4 b = ((const float4*)g_z1)[i];
    float4 c = ((const float4*)g_z2)[i];
    float4 o;
    o.x = b0 * a.x + b1 * b.x + b2 * c.x;
    o.y = b0 * a.y + b1 * b.y + b2 * c.y;
    o.z = b0 * a.z + b1 * b.z + b2 * c.z;
    o.w = b0 * a.w + b1 * b.w + b2 * c.w;
    ((float4*)out)[i] = o;
}

// ---------------- launch ----------------
extern "C" void kernel_launch(void* const* d_in, const int* in_sizes, int n_in,
                              void* d_out, int out_size) {
    const float* h   = (const float*)d_in[0];
    const void*  src = d_in[1];
    const void*  dst = d_in[2];
    const float* W1  = (const float*)d_in[3];
    const float* b1  = (const float*)d_in[4];
    const float* W2  = (const float*)d_in[5];
    float* out = (float*)d_out;

    const int TB = 256;
    int gNF = (NN * FEAT + TB - 1) / TB;          // 6.4M threads
    int gE  = (NP * EE + TB - 1) / TB;            // 9.6M threads
    int gPN = (NP * NN + TB - 1) / TB;
    int gV4 = (NN * 16 + TB - 1) / TB;
    int gH2 = (NP * NN * 32 + TB - 1) / TB;       // all-path half2 slots
    int gG  = (NP * NN * 32 + TB - 1) / TB;       // warp per (path, node)
    dim3 gRS((NN + TB - 1) / TB, NP);             // rowstart scan per path

    k_detect<<<1, 1>>>(src);
    k_init<<<gNF, TB>>>(h);
    k_deg<<<gE, TB>>>(src, dst);
    k_norm<<<gPN, TB>>>();
    k_rowstart<<<gRS, TB>>>();
    k_csrfill<<<gE, TB>>>(src, dst);

    k_scale<<<gH2, TB>>>();
    // ping-pong over all paths at once: A->B, B->A, A->z
    k_gather<<<gG, TB>>>(0);
    k_gather<<<gG, TB>>>(1);
    k_gather<<<gG, TB>>>(2);

    dim3 gF((NN + TB - 1) / TB, NP);
    k_fusion<<<gF, TB>>>(W1, b1, W2);
    k_softmax<<<1, 1>>>();
    k_final<<<gV4, TB>>>(out);
}

// round 17
// speedup vs baseline: 1.1405x; 1.1405x over previous
#include <cuda_runtime.h>
#include <cuda_bf16.h>
#include <cuda_fp16.h>
#include <stdint.h>
#include <math.h>

// Problem constants
#define NN   100000
#define FEAT 64
#define HID  128
#define EE   3200000
#define NP   3
#define ALPHA 0.1f

// ---------------- device scratch (static allocation; no cudaMalloc) ----------------
__device__ __align__(16) float   g_x[NN * FEAT];    // relu(h), also feat0 (fp32)
__device__ __align__(16) float   g_z0[NN * FEAT];   // per-path final features (fp32)
__device__ __align__(16) float   g_z1[NN * FEAT];
__device__ __align__(16) float   g_z2[NN * FEAT];
__device__ __align__(16) __half2 g_hA[NN * 32];     // per-path ping-pong buffers (fp16)
__device__ __align__(16) __half2 g_hB[NN * 32];     //   (pre-scaled by norm_out)
__device__ int   g_csr[NP * EE];      // CSR: src indices grouped by dst
__device__ int   g_rowstart[NP * NN]; // CSR row offsets (per path)
__device__ int   g_fill[NP * NN];     // per-row fill counters
__device__ int   g_ecnt[NP];          // per-path edge counters for block-base grab
__device__ int   g_deg_out[NP * NN];
__device__ int   g_deg_in[NP * NN];
__device__ float g_norm_out[NP * NN];
__device__ float g_norm_in[NP * NN];
__device__ float g_wsum[NP];
__device__ float g_beta[NP];
__device__ int   g_is64;

__device__ __forceinline__ float* zbuf(int p) {
    return p == 0 ? g_z0 : (p == 1 ? g_z1 : g_z2);
}

// two tanh in one MUFU op (operates directly on a half2)
__device__ __forceinline__ __half2 tanh_h2(__half2 x) {
    unsigned int xu = *(unsigned int*)&x;
    unsigned int yu;
    asm("tanh.approx.f16x2 %0, %1;" : "=r"(yu) : "r"(xu));
    return *(__half2*)&yu;
}

// read edge index i from src/dst handling either dtype, clamped to [0, NN)
__device__ __forceinline__ int read_idx(const void* buf, int i) {
    long long v = g_is64 ? ((const long long*)buf)[i] : (long long)((const int*)buf)[i];
    int r = (int)v;
    if (r < 0) r = 0;
    if (r >= NN) r = NN - 1;
    return r;
}

// ---------------- kernels ----------------

// Detect whether index buffers are int64 or int32.
__global__ void k_detect(const void* __restrict__ src) {
    const long long* s64 = (const long long*)src;
    int ok = 1;
    for (int i = 0; i < 64; i++) {
        long long v = s64[i];
        if (v < 0 || v >= NN) { ok = 0; break; }
    }
    g_is64 = ok;
}

// x = relu(h); zero degrees, counters, wsum
__global__ void k_init(const float* __restrict__ h) {
    int i = blockIdx.x * blockDim.x + threadIdx.x;
    if (i < NN * FEAT) {
        g_x[i] = fmaxf(h[i], 0.0f);
    }
    if (i < NP * NN) {
        g_deg_out[i] = 0;
        g_deg_in[i]  = 0;
    }
    if (i < NP) { g_wsum[i] = 0.0f; g_ecnt[i] = 0; }
}

// degree histograms straight from the input buffers
__global__ void k_deg(const void* __restrict__ src,
                      const void* __restrict__ dst) {
    int i = blockIdx.x * blockDim.x + threadIdx.x;
    if (i >= NP * EE) return;
    int p = i / EE;
    int s = read_idx(src, i);
    int d = read_idx(dst, i);
    atomicAdd(&g_deg_out[p * NN + s], 1);
    atomicAdd(&g_deg_in[p * NN + d], 1);
}

// norm = clip(deg,1)^-0.5
__global__ void k_norm() {
    int i = blockIdx.x * blockDim.x + threadIdx.x;
    if (i >= NP * NN) return;
    int dOut = g_deg_out[i]; if (dOut < 1) dOut = 1;
    int dIn  = g_deg_in[i];  if (dIn  < 1) dIn  = 1;
    g_norm_out[i] = rsqrtf((float)dOut);
    g_norm_in[i]  = rsqrtf((float)dIn);
}

// CSR row offsets via in-block scan + one atomic per block (grid.y = path)
__global__ void k_rowstart() {
    __shared__ int s[256];
    __shared__ int base;
    int p   = blockIdx.y;
    int tid = threadIdx.x;
    int n   = blockIdx.x * 256 + tid;
    int d   = (n < NN) ? g_deg_in[p * NN + n] : 0;
    s[tid] = d;
    __syncthreads();
    #pragma unroll
    for (int off = 1; off < 256; off <<= 1) {
        int v = (tid >= off) ? s[tid - off] : 0;
        __syncthreads();
        s[tid] += v;
        __syncthreads();
    }
    if (tid == 255) base = atomicAdd(&g_ecnt[p], s[255]);
    __syncthreads();
    if (n < NN) {
        g_rowstart[p * NN + n] = base + s[tid] - d;  // exclusive offset
        g_fill[p * NN + n] = 0;
    }
}

// CSR fill: scatter src index into its dst row (reads inputs directly)
__global__ void k_csrfill(const void* __restrict__ src,
                          const void* __restrict__ dst) {
    int i = blockIdx.x * blockDim.x + threadIdx.x;
    if (i >= NP * EE) return;
    int p = i / EE;
    int s = read_idx(src, i);
    int d = read_idx(dst, i);
    int idx = p * NN + d;
    int slot = atomicAdd(&g_fill[idx], 1);
    g_csr[p * EE + g_rowstart[idx] + slot] = s;
}

// hA = half2(x * norm_out[p])  (start of each path)
__global__ void k_scale(int p) {
    int i = blockIdx.x * blockDim.x + threadIdx.x;   // half2 granularity: NN*32
    if (i >= NN * 32) return;
    float no = g_norm_out[p * NN + (i >> 5)];
    float2 x = ((const float2*)g_x)[i];
    g_hA[i] = __floats2half2_rn(x.x * no, x.y * no);
}

// gather step: one warp per node. mode 0: A->B, 1: B->A, 2: A->z[p] (last).
// acc(fp32) = sum over in-edges of fin[src](fp16); feat = 0.9*acc*norm_in + 0.1*x;
// non-last: fout = half2(feat*norm_out). Race-free: fin != fout.
__global__ void __launch_bounds__(256) k_gather(int p, int mode) {
    int warp = (blockIdx.x * blockDim.x + threadIdx.x) >> 5;
    if (warp >= NN) return;
    int lane = threadIdx.x & 31;
    int n = warp;
    int idx = p * NN + n;
    int start = g_rowstart[idx];
    int deg   = g_deg_in[idx];
    const int* __restrict__ csr = &g_csr[p * EE + start];
    const __half2* __restrict__ fin = (mode == 1) ? g_hB : g_hA;

    float ax = 0.0f, ay = 0.0f;
    int e = 0;
    for (; e + 4 <= deg; e += 4) {
        int s0 = csr[e], s1 = csr[e + 1], s2 = csr[e + 2], s3 = csr[e + 3];
        float2 v0 = __half22float2(fin[s0 * 32 + lane]);
        float2 v1 = __half22float2(fin[s1 * 32 + lane]);
        float2 v2 = __half22float2(fin[s2 * 32 + lane]);
        float2 v3 = __half22float2(fin[s3 * 32 + lane]);
        ax += (v0.x + v1.x) + (v2.x + v3.x);
        ay += (v0.y + v1.y) + (v2.y + v3.y);
    }
    for (; e < deg; e++) {
        float2 v = __half22float2(fin[csr[e] * 32 + lane]);
        ax += v.x;
        ay += v.y;
    }

    float ni = g_norm_in[idx];
    float2 x = ((const float2*)g_x)[n * 32 + lane];
    float vx = 0.9f * ax * ni + ALPHA * x.x;
    float vy = 0.9f * ay * ni + ALPHA * x.y;
    if (mode == 2) {
        ((float2*)zbuf(p))[n * 32 + lane] = make_float2(vx, vy);
    } else {
        float no = g_norm_out[idx];
        __half2* fout = (mode == 0) ? g_hB : g_hA;
        fout[n * 32 + lane] = __floats2half2_rn(vx * no, vy * no);
    }
}

// semantic fusion scores: wsum[p] += sum_n tanh(z[n,p,:]@W1 + b1) @ W2
// GEMM in half2 (HFMA2, 2 MACs/instr), tanh via tanh.approx.f16x2 on the
// half2 accumulator, final dot in fp32.
__global__ void __launch_bounds__(256) k_fusion(const float* __restrict__ W1,
                                                const float* __restrict__ b1,
                                                const float* __restrict__ W2) {
    __shared__ __half2 sW1h[FEAT * (HID / 2)];  // 16 KB: row k holds 64 half2 (j-pairs)
    __shared__ float sb1[HID];
    __shared__ float sW2[HID];
    __shared__ float sred[256];
    int tid = threadIdx.x;
    for (int i = tid; i < FEAT * (HID / 2); i += 256) {
        int k  = i / (HID / 2);
        int jp = i % (HID / 2);
        sW1h[i] = __floats2half2_rn(W1[k * HID + 2 * jp], W1[k * HID + 2 * jp + 1]);
    }
    if (tid < HID) { sb1[tid] = b1[tid]; sW2[tid] = W2[tid]; }
    __syncthreads();

    int p = blockIdx.y;
    int n = blockIdx.x * 256 + tid;
    float acc = 0.0f;
    if (n < NN) {
        __half2 zb[FEAT];                       // z_k broadcast into both halves
        const float2* zp = (const float2*)zbuf(p);
        #pragma unroll
        for (int i = 0; i < 32; i++) {
            float2 v = zp[n * 32 + i];
            zb[2 * i + 0] = __float2half2_rn(v.x);
            zb[2 * i + 1] = __float2half2_rn(v.y);
        }
        for (int jp = 0; jp < HID / 2; jp += 2) {
            __half2 ha = __floats2half2_rn(sb1[2 * jp],     sb1[2 * jp + 1]);
            __half2 hb = __floats2half2_rn(sb1[2 * jp + 2], sb1[2 * jp + 3]);
            #pragma unroll
            for (int k = 0; k < FEAT; k++) {
                // one 8B smem load feeds two HFMA2
                uint2 w = *(const uint2*)&sW1h[k * (HID / 2) + jp];
                ha = __hfma2(zb[k], *(const __half2*)&w.x, ha);
                hb = __hfma2(zb[k], *(const __half2*)&w.y, hb);
            }
            float2 ta = __half22float2(tanh_h2(ha));
            float2 tb = __half22float2(tanh_h2(hb));
            acc += ta.x * sW2[2 * jp]     + ta.y * sW2[2 * jp + 1]
                 + tb.x * sW2[2 * jp + 2] + tb.y * sW2[2 * jp + 3];
        }
    }
    sred[tid] = acc;
    __syncthreads();
    for (int s = 128; s > 0; s >>= 1) {
        if (tid < s) sred[tid] += sred[tid + s];
        __syncthreads();
    }
    if (tid == 0) atomicAdd(&g_wsum[p], sred[0]);
}

// beta = softmax(wsum / N)
__global__ void k_softmax() {
    float w0 = g_wsum[0] / (float)NN;
    float w1 = g_wsum[1] / (float)NN;
    float w2 = g_wsum[2] / (float)NN;
    float m = fmaxf(w0, fmaxf(w1, w2));
    float e0 = expf(w0 - m), e1 = expf(w1 - m), e2 = expf(w2 - m);
    float s = e0 + e1 + e2;
    g_beta[0] = e0 / s; g_beta[1] = e1 / s; g_beta[2] = e2 / s;
}

// out = sum_p beta[p] * z[p]
__global__ void k_final(float* __restrict__ out) {
    int i = blockIdx.x * blockDim.x + threadIdx.x;   // float4 granularity
    if (i >= NN * 16) return;
    float b0 = g_beta[0], b1 = g_beta[1], b2 = g_beta[2];
    float4 a = ((const float4*)g_z0)[i];
    float4 b = ((const float4*)g_z1)[i];
    float4 c = ((const float4*)g_z2)[i];
    float4 o;
    o.x = b0 * a.x + b1 * b.x + b2 * c.x;
    o.y = b0 * a.y + b1 * b.y + b2 * c.y;
    o.z = b0 * a.z + b1 * b.z + b2 * c.z;
    o.w = b0 * a.w + b1 * b.w + b2 * c.w;
    ((float4*)out)[i] = o;
}

// ---------------- launch ----------------
extern "C" void kernel_launch(void* const* d_in, const int* in_sizes, int n_in,
                              void* d_out, int out_size) {
    const float* h   = (const float*)d_in[0];
    const void*  src = d_in[1];
    const void*  dst = d_in[2];
    const float* W1  = (const float*)d_in[3];
    const float* b1  = (const float*)d_in[4];
    const float* W2  = (const float*)d_in[5];
    float* out = (float*)d_out;

    const int TB = 256;
    int gNF = (NN * FEAT + TB - 1) / TB;      // 6.4M threads
    int gE  = (NP * EE + TB - 1) / TB;        // 9.6M threads
    int gPN = (NP * NN + TB - 1) / TB;
    int gV4 = (NN * 16 + TB - 1) / TB;
    int gH2 = (NN * 32 + TB - 1) / TB;        // half2 granularity (one path)
    int gG  = (NN * 32 + TB - 1) / TB;        // warp per node (one path)
    dim3 gRS((NN + TB - 1) / TB, NP);         // rowstart scan per path

    k_detect<<<1, 1>>>(src);
    k_init<<<gNF, TB>>>(h);
    k_deg<<<gE, TB>>>(src, dst);
    k_norm<<<gPN, TB>>>();
    k_rowstart<<<gRS, TB>>>();
    k_csrfill<<<gE, TB>>>(src, dst);

    // per-path propagation keeps the gather working set L2-resident
    for (int p = 0; p < NP; p++) {
        k_scale<<<gH2, TB>>>(p);
        // ping-pong: step0 A->B, step1 B->A, step2 (last) A->z[p]
        k_gather<<<gG, TB>>>(p, 0);
        k_gather<<<gG, TB>>>(p, 1);
        k_gather<<<gG, TB>>>(p, 2);
    }

    dim3 gF((NN + TB - 1) / TB, NP);
    k_fusion<<<gF, TB>>>(W1, b1, W2);
    k_softmax<<<1, 1>>>();
    k_final<<<gV4, TB>>>(out);
}